// round 9
// baseline (speedup 1.0000x reference)
#include <cuda_runtime.h>
#include <cuda_bf16.h>
#include <cstdint>

// ----------------------------------------------------------------------------
// VGG16 RoI head:
//   pool  = adaptive ROI maxpool(x, rois)          [300, 512*7*7 = 25088]
//   fc6   = relu(pool @ W_fc6 + b_fc6)             [300, 4096]
//   fc7   = relu(fc6  @ W_fc7 + b_fc7)             [300, 4096]
//   loc   = fc7 @ W_loc + b_loc                    [300, 84]
//   score = fc7 @ W_score + b_score                [300, 21]
// Output: concat(loc.flatten(), score.flatten())   31500 floats
// ----------------------------------------------------------------------------

#define R_ROIS   300
#define CCH      512
#define HF       50
#define WF       50
#define NPOOL    (CCH * 49)          // 25088
#define NFC      4096
#define NLOC     84
#define NSCORE   21

// -------------------- device scratch (no allocations allowed) ---------------
__device__ float g_pool[R_ROIS * NPOOL];   // ~30.1 MB
__device__ float g_fc6 [R_ROIS * NFC];     // ~4.9 MB
__device__ float g_fc7 [R_ROIS * NFC];     // ~4.9 MB

// ----------------------------- ROI max pool ---------------------------------
// Matches: y1=int(roi*1/16) (trunc); h=y2-y1+1; bins rs=floor(i*h/7),
// re=ceil((i+1)*h/7); max over [rs,re) x [cs,ce). Multiply by 0.0625f is a
// pure exponent shift -> exact, so int casts match the reference bitwise.
__global__ void roi_pool_kernel(const float* __restrict__ feat,
                                const float* __restrict__ rois,
                                float* __restrict__ out)
{
    int idx = blockIdx.x * blockDim.x + threadIdx.x;
    if (idx >= R_ROIS * NPOOL) return;
    int r    = idx / NPOOL;
    int rem  = idx - r * NPOOL;
    int c    = rem / 49;
    int bin  = rem - c * 49;
    int by   = bin / 7;
    int bx   = bin - by * 7;

    int y1 = (int)(rois[r * 4 + 0] * 0.0625f);
    int x1 = (int)(rois[r * 4 + 1] * 0.0625f);
    int y2 = (int)(rois[r * 4 + 2] * 0.0625f);
    int x2 = (int)(rois[r * 4 + 3] * 0.0625f);
    int h = y2 - y1 + 1;
    int w = x2 - x1 + 1;

    int rs = y1 + (by * h) / 7;
    int re = y1 + ((by + 1) * h + 6) / 7;
    int cs = x1 + (bx * w) / 7;
    int ce = x1 + ((bx + 1) * w + 6) / 7;

    const float* fp = feat + c * (HF * WF);
    float m = -3.402823466e38f;
    for (int y = rs; y < re; ++y) {
        const float* rowp = fp + y * WF;
        for (int x = cs; x < ce; ++x)
            m = fmaxf(m, rowp[x]);
    }
    out[idx] = m;   // layout [r][c*49 + by*7 + bx] == reshape(R, C*7*7)
}

// ---------------------- tf32 mma.sync GEMM (fp32 accum) ---------------------
// C[M,N] = relu?(A[M,K] @ B[K,N] + bias[N])
// Block tile 64x128, BK=16, 8 warps (2x4), warp tile 32x32.
// cp.async double-buffered smem; bank-conflict-free padded strides.
#define BM 64
#define BN 128
#define BK 16
#define AS_STRIDE 20    // 64 rows * 20 floats  (20*g mod 32 covers all groups)
#define BS_STRIDE 136   // 16 rows * 136 floats (8*tg + g distinct banks)

__device__ __forceinline__ uint32_t f2tf32(float f) {
    uint32_t r;
    asm("cvt.rna.tf32.f32 %0, %1;" : "=r"(r) : "f"(f));
    return r;
}

__device__ __forceinline__ void cp_async16(float* smem_dst, const float* gmem_src, bool pred) {
    uint32_t s = (uint32_t)__cvta_generic_to_shared(smem_dst);
    int sz = pred ? 16 : 0;  // src-size 0 => zero-fill 16B, no global read
    asm volatile("cp.async.cg.shared.global [%0], [%1], 16, %2;"
                 :: "r"(s), "l"(gmem_src), "r"(sz));
}

__device__ __forceinline__ void mma_tf32(float c[4],
                                         uint32_t a0, uint32_t a1, uint32_t a2, uint32_t a3,
                                         uint32_t b0, uint32_t b1) {
    asm volatile(
        "mma.sync.aligned.m16n8k8.row.col.f32.tf32.tf32.f32 "
        "{%0,%1,%2,%3}, {%4,%5,%6,%7}, {%8,%9}, {%0,%1,%2,%3};"
        : "+f"(c[0]), "+f"(c[1]), "+f"(c[2]), "+f"(c[3])
        : "r"(a0), "r"(a1), "r"(a2), "r"(a3), "r"(b0), "r"(b1));
}

__global__ __launch_bounds__(256, 2)
void gemm_tf32_kernel(const float* __restrict__ A,
                      const float* __restrict__ B,
                      const float* __restrict__ bias,
                      float* __restrict__ C,
                      int M, int N, int K, int do_relu)
{
    __shared__ float As[2][BM * AS_STRIDE];
    __shared__ float Bs[2][BK * BS_STRIDE];

    const int tid  = threadIdx.x;
    const int m0   = blockIdx.y * BM;
    const int n0   = blockIdx.x * BN;
    const int warp = tid >> 5;
    const int lane = tid & 31;
    const int wm   = warp >> 2;     // 0..1
    const int wn   = warp & 3;      // 0..3
    const int g    = lane >> 2;     // 0..7
    const int tg   = lane & 3;      // 0..3

    // A tile load: thread -> (row = tid/4, 16B chunk = tid%4)
    const int arow = tid >> 2;
    const int ac4  = tid & 3;
    const bool apred = (m0 + arow) < M;
    const float* Agbase = A + (size_t)(m0 + arow) * K + ac4 * 4;

    // B tile load: two float4 per thread: (row=tid/32, col4=tid%32) and (+8 rows)
    const int brow0 = tid >> 5;
    const int bc4   = tid & 31;
    const float* Bgbase0 = B + (size_t)brow0 * N + n0 + bc4 * 4;
    const float* Bgbase1 = B + (size_t)(brow0 + 8) * N + n0 + bc4 * 4;

    float acc[2][4][4];
    #pragma unroll
    for (int mi = 0; mi < 2; ++mi)
        #pragma unroll
        for (int ni = 0; ni < 4; ++ni)
            #pragma unroll
            for (int q = 0; q < 4; ++q) acc[mi][ni][q] = 0.0f;

    const int T = K / BK;

    // prologue: stage tile 0
    {
        cp_async16(&As[0][arow * AS_STRIDE + ac4 * 4], Agbase, apred);
        cp_async16(&Bs[0][brow0 * BS_STRIDE + bc4 * 4], Bgbase0, true);
        cp_async16(&Bs[0][(brow0 + 8) * BS_STRIDE + bc4 * 4], Bgbase1, true);
        asm volatile("cp.async.commit_group;");
    }

    for (int t = 0; t < T; ++t) {
        const int cur = t & 1;
        if (t + 1 < T) {
            const int nxt = (t + 1) & 1;
            const size_t koff = (size_t)(t + 1) * BK;
            cp_async16(&As[nxt][arow * AS_STRIDE + ac4 * 4], Agbase + koff, apred);
            cp_async16(&Bs[nxt][brow0 * BS_STRIDE + bc4 * 4], Bgbase0 + koff * N, true);
            cp_async16(&Bs[nxt][(brow0 + 8) * BS_STRIDE + bc4 * 4], Bgbase1 + koff * N, true);
        }
        asm volatile("cp.async.commit_group;");
        asm volatile("cp.async.wait_group 1;");
        __syncthreads();

        const float* Asc = As[cur];
        const float* Bsc = Bs[cur];
        #pragma unroll
        for (int kk = 0; kk < BK; kk += 8) {
            uint32_t af[2][4], bf[4][2];
            #pragma unroll
            for (int mi = 0; mi < 2; ++mi) {
                const int rb = wm * 32 + mi * 16;
                af[mi][0] = f2tf32(Asc[(rb + g)     * AS_STRIDE + kk + tg]);
                af[mi][1] = f2tf32(Asc[(rb + g + 8) * AS_STRIDE + kk + tg]);
                af[mi][2] = f2tf32(Asc[(rb + g)     * AS_STRIDE + kk + tg + 4]);
                af[mi][3] = f2tf32(Asc[(rb + g + 8) * AS_STRIDE + kk + tg + 4]);
            }
            #pragma unroll
            for (int ni = 0; ni < 4; ++ni) {
                const int cb = wn * 32 + ni * 8;
                bf[ni][0] = f2tf32(Bsc[(kk + tg)     * BS_STRIDE + cb + g]);
                bf[ni][1] = f2tf32(Bsc[(kk + tg + 4) * BS_STRIDE + cb + g]);
            }
            #pragma unroll
            for (int mi = 0; mi < 2; ++mi)
                #pragma unroll
                for (int ni = 0; ni < 4; ++ni)
                    mma_tf32(acc[mi][ni], af[mi][0], af[mi][1], af[mi][2], af[mi][3],
                             bf[ni][0], bf[ni][1]);
        }
        __syncthreads();
    }

    // epilogue: bias + relu + bounds-checked store
    #pragma unroll
    for (int mi = 0; mi < 2; ++mi) {
        #pragma unroll
        for (int ni = 0; ni < 4; ++ni) {
            const int row0 = m0 + wm * 32 + mi * 16 + g;
            const int col  = n0 + wn * 32 + ni * 8 + 2 * tg;
            const float bv0 = bias[col];
            const float bv1 = bias[col + 1];
            float v00 = acc[mi][ni][0] + bv0;
            float v01 = acc[mi][ni][1] + bv1;
            float v10 = acc[mi][ni][2] + bv0;
            float v11 = acc[mi][ni][3] + bv1;
            if (do_relu) {
                v00 = fmaxf(v00, 0.0f); v01 = fmaxf(v01, 0.0f);
                v10 = fmaxf(v10, 0.0f); v11 = fmaxf(v11, 0.0f);
            }
            if (row0 < M) {
                C[(size_t)row0 * N + col]     = v00;
                C[(size_t)row0 * N + col + 1] = v01;
            }
            if (row0 + 8 < M) {
                C[(size_t)(row0 + 8) * N + col]     = v10;
                C[(size_t)(row0 + 8) * N + col + 1] = v11;
            }
        }
    }
}

// ------------------------------- heads (fp32) -------------------------------
// One block per 4 rois; thread t owns output column t (0..83 -> loc, 84..104 ->
// score). fc7 rows staged through smem in K-chunks; W columns read coalesced.
__global__ __launch_bounds__(128)
void heads_kernel(const float* __restrict__ fc7,
                  const float* __restrict__ Wl, const float* __restrict__ bl,
                  const float* __restrict__ Ws, const float* __restrict__ bs,
                  float* __restrict__ out)
{
    __shared__ float Ash[4][1024];
    const int t  = threadIdx.x;
    const int r0 = blockIdx.x * 4;

    const float* Wp = nullptr;
    int ldw = 0, col = 0;
    if (t < 84)       { Wp = Wl; ldw = NLOC;   col = t; }
    else if (t < 105) { Wp = Ws; ldw = NSCORE; col = t - 84; }

    float acc0 = 0.f, acc1 = 0.f, acc2 = 0.f, acc3 = 0.f;

    for (int kc = 0; kc < NFC; kc += 1024) {
        __syncthreads();
        #pragma unroll
        for (int j = 0; j < 4; ++j) {
            const float4* src = (const float4*)(fc7 + (size_t)(r0 + j) * NFC + kc);
            for (int i = t; i < 256; i += 128)
                ((float4*)&Ash[j][0])[i] = src[i];
        }
        __syncthreads();
        if (t < 105) {
            const float* wptr = Wp + (size_t)kc * ldw + col;
            #pragma unroll 4
            for (int k = 0; k < 1024; ++k) {
                const float w = wptr[(size_t)k * ldw];
                acc0 = fmaf(Ash[0][k], w, acc0);
                acc1 = fmaf(Ash[1][k], w, acc1);
                acc2 = fmaf(Ash[2][k], w, acc2);
                acc3 = fmaf(Ash[3][k], w, acc3);
            }
        }
    }

    if (t < 84) {
        const float b = bl[t];
        out[(size_t)(r0 + 0) * NLOC + t] = acc0 + b;
        out[(size_t)(r0 + 1) * NLOC + t] = acc1 + b;
        out[(size_t)(r0 + 2) * NLOC + t] = acc2 + b;
        out[(size_t)(r0 + 3) * NLOC + t] = acc3 + b;
    } else if (t < 105) {
        const int c = t - 84;
        const float b = bs[c];
        float* so = out + R_ROIS * NLOC;
        so[(size_t)(r0 + 0) * NSCORE + c] = acc0 + b;
        so[(size_t)(r0 + 1) * NSCORE + c] = acc1 + b;
        so[(size_t)(r0 + 2) * NSCORE + c] = acc2 + b;
        so[(size_t)(r0 + 3) * NSCORE + c] = acc3 + b;
    }
}

// ------------------------------- launch -------------------------------------
extern "C" void kernel_launch(void* const* d_in, const int* in_sizes, int n_in,
                              void* d_out, int out_size)
{
    (void)in_sizes; (void)n_in; (void)out_size;
    const float* x     = (const float*)d_in[0];
    const float* rois  = (const float*)d_in[1];
    const float* W6    = (const float*)d_in[2];
    const float* b6    = (const float*)d_in[3];
    const float* W7    = (const float*)d_in[4];
    const float* b7    = (const float*)d_in[5];
    const float* Wl    = (const float*)d_in[6];
    const float* bl    = (const float*)d_in[7];
    const float* Ws    = (const float*)d_in[8];
    const float* bs    = (const float*)d_in[9];
    float* out = (float*)d_out;

    float *pool_p, *fc6_p, *fc7_p;
    cudaGetSymbolAddress((void**)&pool_p, g_pool);
    cudaGetSymbolAddress((void**)&fc6_p,  g_fc6);
    cudaGetSymbolAddress((void**)&fc7_p,  g_fc7);

    // 1) ROI adaptive maxpool
    {
        const int total = R_ROIS * NPOOL;
        roi_pool_kernel<<<(total + 255) / 256, 256>>>(x, rois, pool_p);
    }
    // 2) fc6 = relu(pool @ W6 + b6)   M=300 N=4096 K=25088
    {
        dim3 grid(NFC / BN, (R_ROIS + BM - 1) / BM);
        gemm_tf32_kernel<<<grid, 256>>>(pool_p, W6, b6, fc6_p, R_ROIS, NFC, NPOOL, 1);
    }
    // 3) fc7 = relu(fc6 @ W7 + b7)    M=300 N=4096 K=4096
    {
        dim3 grid(NFC / BN, (R_ROIS + BM - 1) / BM);
        gemm_tf32_kernel<<<grid, 256>>>(fc6_p, W7, b7, fc7_p, R_ROIS, NFC, NFC, 1);
    }
    // 4) heads (fp32): loc + score, writes full d_out
    heads_kernel<<<R_ROIS / 4, 128>>>(fc7_p, Wl, bl, Ws, bs, out);
}

// round 11
// speedup vs baseline: 1.8347x; 1.8347x over previous
#include <cuda_runtime.h>
#include <cuda_bf16.h>
#include <cstdint>

// ----------------------------------------------------------------------------
// VGG16 RoI head:
//   pool  = adaptive ROI maxpool(x, rois)          [300, 512*7*7 = 25088]
//   fc6   = relu(pool @ W_fc6 + b_fc6)             [300, 4096]
//   fc7   = relu(fc6  @ W_fc7 + b_fc7)             [300, 4096]
//   loc   = fc7 @ W_loc + b_loc                    [300, 84]
//   score = fc7 @ W_score + b_score                [300, 21]
// Output: concat(loc.flatten(), score.flatten())   31500 floats
// ----------------------------------------------------------------------------

#define R_ROIS   300
#define CCH      512
#define HF       50
#define WF       50
#define NPOOL    (CCH * 49)          // 25088
#define NFC      4096
#define NLOC     84
#define NSCORE   21
#define NHEAD    (NLOC + NSCORE)     // 105
#define KSPLIT   8                   // heads split-K factor (4096/8 = 512)

// -------------------- device scratch (no allocations allowed) ---------------
__device__ float g_pool [R_ROIS * NPOOL];          // ~30.1 MB
__device__ float g_fc6  [R_ROIS * NFC];            // ~4.9 MB
__device__ float g_fc7  [R_ROIS * NFC];            // ~4.9 MB
__device__ float g_hpart[KSPLIT * R_ROIS * NHEAD]; // ~1.0 MB

// ----------------------------- ROI max pool ---------------------------------
// Matches reference: y1=int(roi/16) (trunc; *0.0625f exact), h=y2-y1+1,
// bins rs=floor(i*h/7), re=ceil((i+1)*h/7); max over [rs,re)x[cs,ce).
__global__ void roi_pool_kernel(const float* __restrict__ feat,
                                const float* __restrict__ rois,
                                float* __restrict__ out)
{
    int idx = blockIdx.x * blockDim.x + threadIdx.x;
    if (idx >= R_ROIS * NPOOL) return;
    int r    = idx / NPOOL;
    int rem  = idx - r * NPOOL;
    int c    = rem / 49;
    int bin  = rem - c * 49;
    int by   = bin / 7;
    int bx   = bin - by * 7;

    int y1 = (int)(rois[r * 4 + 0] * 0.0625f);
    int x1 = (int)(rois[r * 4 + 1] * 0.0625f);
    int y2 = (int)(rois[r * 4 + 2] * 0.0625f);
    int x2 = (int)(rois[r * 4 + 3] * 0.0625f);
    int h = y2 - y1 + 1;
    int w = x2 - x1 + 1;

    int rs = y1 + (by * h) / 7;
    int re = y1 + ((by + 1) * h + 6) / 7;
    int cs = x1 + (bx * w) / 7;
    int ce = x1 + ((bx + 1) * w + 6) / 7;

    const float* fp = feat + c * (HF * WF);
    float m = -3.402823466e38f;
    for (int y = rs; y < re; ++y) {
        const float* rowp = fp + y * WF;
        for (int x = cs; x < ce; ++x)
            m = fmaxf(m, rowp[x]);
    }
    out[idx] = m;   // [r][c*49 + by*7 + bx] == reshape(R, C*7*7)
}

// ---------------------- tf32 mma.sync GEMM (fp32 accum) ---------------------
// C[M,N] = relu?(A[M,K] @ B[K,N] + bias[N])
// Block tile 64x128, BK=16, 4 warps (2x2), warp tile 32x64 (mi=2, ni=8).
// 3-stage cp.async pipeline, one __syncthreads per BK tile.
#define BM 64
#define BN 128
#define BK 16
#define AS_STRIDE 20    // (20*g + tg) mod 32 covers all banks
#define BS_STRIDE 136   // (8*tg + g) mod 32 covers all banks

__device__ __forceinline__ uint32_t f2tf32(float f) {
    uint32_t r;
    asm("cvt.rna.tf32.f32 %0, %1;" : "=r"(r) : "f"(f));
    return r;
}

__device__ __forceinline__ void cp_async16(float* smem_dst, const float* gmem_src, bool pred) {
    uint32_t s = (uint32_t)__cvta_generic_to_shared(smem_dst);
    int sz = pred ? 16 : 0;  // src-size 0 => zero-fill 16B, no global read
    asm volatile("cp.async.cg.shared.global [%0], [%1], 16, %2;"
                 :: "r"(s), "l"(gmem_src), "r"(sz));
}

__device__ __forceinline__ void mma_tf32(float c[4],
                                         uint32_t a0, uint32_t a1, uint32_t a2, uint32_t a3,
                                         uint32_t b0, uint32_t b1) {
    asm volatile(
        "mma.sync.aligned.m16n8k8.row.col.f32.tf32.tf32.f32 "
        "{%0,%1,%2,%3}, {%4,%5,%6,%7}, {%8,%9}, {%0,%1,%2,%3};"
        : "+f"(c[0]), "+f"(c[1]), "+f"(c[2]), "+f"(c[3])
        : "r"(a0), "r"(a1), "r"(a2), "r"(a3), "r"(b0), "r"(b1));
}

__global__ __launch_bounds__(128, 2)
void gemm_tf32_kernel(const float* __restrict__ A,
                      const float* __restrict__ B,
                      const float* __restrict__ bias,
                      float* __restrict__ C,
                      int M, int N, int K, int do_relu)
{
    __shared__ float As[3][BM * AS_STRIDE];
    __shared__ float Bs[3][BK * BS_STRIDE];

    const int tid  = threadIdx.x;
    const int m0   = blockIdx.y * BM;
    const int n0   = blockIdx.x * BN;
    const int warp = tid >> 5;
    const int lane = tid & 31;
    const int wm   = warp >> 1;     // 0..1
    const int wn   = warp & 1;      // 0..1
    const int g    = lane >> 2;     // 0..7
    const int tg   = lane & 3;      // 0..3

    // A staging: thread -> (row = tid/2, two 16B chunks)
    const int arow = tid >> 1;
    const int ac0  = (tid & 1) * 2;              // chunk pair start (0 or 2)
    const bool apred = (m0 + arow) < M;
    const float* AgBase = A + (size_t)(m0 + arow) * K + ac0 * 4;
    float* AsBase0 = nullptr;  // per-stage below

    // B staging: thread -> (row = tid/8, 4 chunks j*8 + (tid&7))
    const int brow = tid >> 3;                   // 0..15
    const int bc   = tid & 7;                    // 0..7
    const float* BgBase = B + (size_t)brow * N + n0 + bc * 4;

    float acc[2][8][4];
    #pragma unroll
    for (int mi = 0; mi < 2; ++mi)
        #pragma unroll
        for (int ni = 0; ni < 8; ++ni)
            #pragma unroll
            for (int q = 0; q < 4; ++q) acc[mi][ni][q] = 0.0f;

    const int T = K / BK;

    // ---- stage loader ----
    auto stage = [&](int buf, int ts) {
        const size_t ka = (size_t)ts * BK;
        cp_async16(&As[buf][arow * AS_STRIDE + ac0 * 4],     AgBase + ka,     apred);
        cp_async16(&As[buf][arow * AS_STRIDE + ac0 * 4 + 4], AgBase + ka + 4, apred);
        const size_t kb = ka * (size_t)N;
        #pragma unroll
        for (int j = 0; j < 4; ++j)
            cp_async16(&Bs[buf][brow * BS_STRIDE + (j * 8 + bc) * 4],
                       BgBase + kb + j * 32, true);
    };

    // prologue: stages 0 and 1
    stage(0, 0);
    asm volatile("cp.async.commit_group;");
    stage(1, 1);
    asm volatile("cp.async.commit_group;");

    int cur = 0;
    for (int t = 0; t < T; ++t) {
        asm volatile("cp.async.wait_group 1;");  // stage t resident
        __syncthreads();                          // all warps past compute(t-1)

        // issue stage t+2 into buffer (t+2)%3 (== (t-1)%3, now free)
        if (t + 2 < T) {
            int nxt = cur + 2; if (nxt >= 3) nxt -= 3;
            stage(nxt, t + 2);
        }
        asm volatile("cp.async.commit_group;");

        const float* Asc = As[cur];
        const float* Bsc = Bs[cur];
        #pragma unroll
        for (int kk = 0; kk < BK; kk += 8) {
            uint32_t af[2][4], bf[8][2];
            #pragma unroll
            for (int mi = 0; mi < 2; ++mi) {
                const int rb = wm * 32 + mi * 16;
                af[mi][0] = f2tf32(Asc[(rb + g)     * AS_STRIDE + kk + tg]);
                af[mi][1] = f2tf32(Asc[(rb + g + 8) * AS_STRIDE + kk + tg]);
                af[mi][2] = f2tf32(Asc[(rb + g)     * AS_STRIDE + kk + tg + 4]);
                af[mi][3] = f2tf32(Asc[(rb + g + 8) * AS_STRIDE + kk + tg + 4]);
            }
            #pragma unroll
            for (int ni = 0; ni < 8; ++ni) {
                const int cb = wn * 64 + ni * 8;
                bf[ni][0] = f2tf32(Bsc[(kk + tg)     * BS_STRIDE + cb + g]);
                bf[ni][1] = f2tf32(Bsc[(kk + tg + 4) * BS_STRIDE + cb + g]);
            }
            #pragma unroll
            for (int mi = 0; mi < 2; ++mi)
                #pragma unroll
                for (int ni = 0; ni < 8; ++ni)
                    mma_tf32(acc[mi][ni], af[mi][0], af[mi][1], af[mi][2], af[mi][3],
                             bf[ni][0], bf[ni][1]);
        }
        ++cur; if (cur == 3) cur = 0;
    }

    // epilogue: bias + relu + bounds-checked store
    #pragma unroll
    for (int mi = 0; mi < 2; ++mi) {
        #pragma unroll
        for (int ni = 0; ni < 8; ++ni) {
            const int row0 = m0 + wm * 32 + mi * 16 + g;
            const int col  = n0 + wn * 64 + ni * 8 + 2 * tg;
            const float bv0 = bias[col];
            const float bv1 = bias[col + 1];
            float v00 = acc[mi][ni][0] + bv0;
            float v01 = acc[mi][ni][1] + bv1;
            float v10 = acc[mi][ni][2] + bv0;
            float v11 = acc[mi][ni][3] + bv1;
            if (do_relu) {
                v00 = fmaxf(v00, 0.0f); v01 = fmaxf(v01, 0.0f);
                v10 = fmaxf(v10, 0.0f); v11 = fmaxf(v11, 0.0f);
            }
            if (row0 < M) {
                C[(size_t)row0 * N + col]     = v00;
                C[(size_t)row0 * N + col + 1] = v01;
            }
            if (row0 + 8 < M) {
                C[(size_t)(row0 + 8) * N + col]     = v10;
                C[(size_t)(row0 + 8) * N + col + 1] = v11;
            }
        }
    }
}

// ------------------------------- heads (fp32) -------------------------------
// Split-K: grid (KSPLIT, 75). Block = 4 rois x 512-wide K slice, 128 threads.
// Thread t (<105) owns output column t (coalesced W reads across threads).
// Partials to g_hpart; deterministic fixed-order reduce adds bias.
__global__ __launch_bounds__(128)
void heads_part_kernel(const float* __restrict__ fc7,
                       const float* __restrict__ Wl,
                       const float* __restrict__ Ws,
                       float* __restrict__ part)
{
    __shared__ float Ash[4][512];
    const int t  = threadIdx.x;
    const int kp = blockIdx.x;
    const int k0 = kp * (NFC / KSPLIT);      // 512-wide slice
    const int r0 = blockIdx.y * 4;

    // stage fc7[r0..r0+3][k0..k0+511]
    #pragma unroll
    for (int j = 0; j < 4; ++j) {
        const float4* src = (const float4*)(fc7 + (size_t)(r0 + j) * NFC + k0);
        ((float4*)&Ash[j][0])[t] = src[t];   // 128 float4 = 512 floats
    }
    __syncthreads();

    if (t < NHEAD) {
        const float* Wp; int ldw, col;
        if (t < NLOC) { Wp = Wl; ldw = NLOC;   col = t; }
        else          { Wp = Ws; ldw = NSCORE; col = t - NLOC; }
        const float* wptr = Wp + (size_t)k0 * ldw + col;

        float a0 = 0.f, a1 = 0.f, a2 = 0.f, a3 = 0.f;
        #pragma unroll 8
        for (int k = 0; k < 512; ++k) {
            const float w = __ldg(wptr + (size_t)k * ldw);
            a0 = fmaf(Ash[0][k], w, a0);
            a1 = fmaf(Ash[1][k], w, a1);
            a2 = fmaf(Ash[2][k], w, a2);
            a3 = fmaf(Ash[3][k], w, a3);
        }
        float* pp = part + (size_t)kp * (R_ROIS * NHEAD) + (size_t)r0 * NHEAD + t;
        pp[0 * NHEAD] = a0;
        pp[1 * NHEAD] = a1;
        pp[2 * NHEAD] = a2;
        pp[3 * NHEAD] = a3;
    }
}

__global__ void heads_reduce_kernel(const float* __restrict__ part,
                                    const float* __restrict__ bl,
                                    const float* __restrict__ bs,
                                    float* __restrict__ out)
{
    int idx = blockIdx.x * blockDim.x + threadIdx.x;
    if (idx >= R_ROIS * NHEAD) return;
    float s = 0.f;
    #pragma unroll
    for (int p = 0; p < KSPLIT; ++p)
        s += part[(size_t)p * (R_ROIS * NHEAD) + idx];
    const int roi = idx / NHEAD;
    const int c   = idx - roi * NHEAD;
    if (c < NLOC)
        out[(size_t)roi * NLOC + c] = s + bl[c];
    else
        out[(size_t)R_ROIS * NLOC + (size_t)roi * NSCORE + (c - NLOC)] = s + bs[c - NLOC];
}

// ------------------------------- launch -------------------------------------
extern "C" void kernel_launch(void* const* d_in, const int* in_sizes, int n_in,
                              void* d_out, int out_size)
{
    (void)in_sizes; (void)n_in; (void)out_size;
    const float* x     = (const float*)d_in[0];
    const float* rois  = (const float*)d_in[1];
    const float* W6    = (const float*)d_in[2];
    const float* b6    = (const float*)d_in[3];
    const float* W7    = (const float*)d_in[4];
    const float* b7    = (const float*)d_in[5];
    const float* Wl    = (const float*)d_in[6];
    const float* bl    = (const float*)d_in[7];
    const float* Ws    = (const float*)d_in[8];
    const float* bs    = (const float*)d_in[9];
    float* out = (float*)d_out;

    float *pool_p, *fc6_p, *fc7_p, *hpart_p;
    cudaGetSymbolAddress((void**)&pool_p,  g_pool);
    cudaGetSymbolAddress((void**)&fc6_p,   g_fc6);
    cudaGetSymbolAddress((void**)&fc7_p,   g_fc7);
    cudaGetSymbolAddress((void**)&hpart_p, g_hpart);

    // 1) ROI adaptive maxpool
    {
        const int total = R_ROIS * NPOOL;
        roi_pool_kernel<<<(total + 255) / 256, 256>>>(x, rois, pool_p);
    }
    // 2) fc6 = relu(pool @ W6 + b6)   M=300 N=4096 K=25088
    {
        dim3 grid(NFC / BN, (R_ROIS + BM - 1) / BM);
        gemm_tf32_kernel<<<grid, 128>>>(pool_p, W6, b6, fc6_p, R_ROIS, NFC, NPOOL, 1);
    }
    // 3) fc7 = relu(fc6 @ W7 + b7)    M=300 N=4096 K=4096
    {
        dim3 grid(NFC / BN, (R_ROIS + BM - 1) / BM);
        gemm_tf32_kernel<<<grid, 128>>>(fc6_p, W7, b7, fc7_p, R_ROIS, NFC, NFC, 1);
    }
    // 4) heads: split-K partials + deterministic reduce (writes full d_out)
    {
        dim3 grid(KSPLIT, R_ROIS / 4);
        heads_part_kernel<<<grid, 128>>>(fc7_p, Wl, Ws, hpart_p);
        heads_reduce_kernel<<<(R_ROIS * NHEAD + 255) / 256, 256>>>(hpart_p, bl, bs, out);
    }
}

// round 15
// speedup vs baseline: 2.5579x; 1.3941x over previous
#include <cuda_runtime.h>
#include <cuda_bf16.h>
#include <cstdint>

// ----------------------------------------------------------------------------
// VGG16 RoI head: pool -> fc6(relu) -> fc7(relu) -> {loc, score}
// GEMMs on mma.sync.m16n8k8.tf32 (sm_103 base ISA — tcgen05 is 'a'-suffix and
// NOT available in this toolchain config; verified by R14 ptxas failure).
// Split-K=2 on both GEMMs for 2 CTAs/SM occupancy; A operands pre-rounded to
// tf32 so the mainloop has no A-side cvt.
// ----------------------------------------------------------------------------

#define R_ROIS   300
#define CCH      512
#define HF       50
#define WF       50
#define NPOOL    (CCH * 49)          // 25088
#define NFC      4096
#define NLOC     84
#define NSCORE   21
#define NHEAD    (NLOC + NSCORE)     // 105
#define KSPLIT   8                   // heads split-K
#define GSPLIT   2                   // gemm split-K

// -------------------- device scratch (no allocations allowed) ---------------
__device__ float g_pool [R_ROIS * NPOOL];            // ~30.1 MB
__device__ float g_fc6  [R_ROIS * NFC];              // ~4.9 MB
__device__ float g_fc7  [R_ROIS * NFC];              // ~4.9 MB
__device__ float g_part [GSPLIT * R_ROIS * NFC];     // ~9.8 MB gemm partials
__device__ float g_hpart[KSPLIT * R_ROIS * NHEAD];   // ~1.0 MB

__device__ __forceinline__ uint32_t f2tf32(float f) {
    uint32_t r;
    asm("cvt.rna.tf32.f32 %0, %1;" : "=r"(r) : "f"(f));
    return r;
}

// ----------------------------- ROI max pool ---------------------------------
// Output pre-rounded to tf32: identical numerics to rounding A inside the
// GEMM (what R11 did), but removes the cvt from the GEMM hot loop.
__global__ void roi_pool_kernel(const float* __restrict__ feat,
                                const float* __restrict__ rois,
                                float* __restrict__ out)
{
    int idx = blockIdx.x * blockDim.x + threadIdx.x;
    if (idx >= R_ROIS * NPOOL) return;
    int r    = idx / NPOOL;
    int rem  = idx - r * NPOOL;
    int c    = rem / 49;
    int bin  = rem - c * 49;
    int by   = bin / 7;
    int bx   = bin - by * 7;

    int y1 = (int)(rois[r * 4 + 0] * 0.0625f);
    int x1 = (int)(rois[r * 4 + 1] * 0.0625f);
    int y2 = (int)(rois[r * 4 + 2] * 0.0625f);
    int x2 = (int)(rois[r * 4 + 3] * 0.0625f);
    int h = y2 - y1 + 1;
    int w = x2 - x1 + 1;

    int rs = y1 + (by * h) / 7;
    int re = y1 + ((by + 1) * h + 6) / 7;
    int cs = x1 + (bx * w) / 7;
    int ce = x1 + ((bx + 1) * w + 6) / 7;

    const float* fp = feat + c * (HF * WF);
    float m = -3.402823466e38f;
    for (int y = rs; y < re; ++y) {
        const float* rowp = fp + y * WF;
        for (int x = cs; x < ce; ++x)
            m = fmaxf(m, rowp[x]);
    }
    out[idx] = __uint_as_float(f2tf32(m));
}

// ---------------------- tf32 mma.sync GEMM (fp32 accum) ---------------------
// Cpart[M,N] = A[M, k0:k0+KP] @ B[k0:k0+KP, N]   (raw partial, no epilogue)
// Block tile 64x128, BK=16, 4 warps (2x2), warp tile 32x64 (mi=2, ni=8).
// 3-stage cp.async pipeline, one __syncthreads per BK tile.
// A in gmem is ALREADY tf32-rounded -> A fragments load raw (no cvt).
#define BM 64
#define BN 128
#define BK 16
#define AS_STRIDE 20
#define BS_STRIDE 136

__device__ __forceinline__ void cp_async16(float* smem_dst, const float* gmem_src, bool pred) {
    uint32_t s = (uint32_t)__cvta_generic_to_shared(smem_dst);
    int sz = pred ? 16 : 0;  // src-size 0 => zero-fill 16B (0.0f is valid tf32)
    asm volatile("cp.async.cg.shared.global [%0], [%1], 16, %2;"
                 :: "r"(s), "l"(gmem_src), "r"(sz));
}

__device__ __forceinline__ void mma_tf32(float c[4],
                                         uint32_t a0, uint32_t a1, uint32_t a2, uint32_t a3,
                                         uint32_t b0, uint32_t b1) {
    asm volatile(
        "mma.sync.aligned.m16n8k8.row.col.f32.tf32.tf32.f32 "
        "{%0,%1,%2,%3}, {%4,%5,%6,%7}, {%8,%9}, {%0,%1,%2,%3};"
        : "+f"(c[0]), "+f"(c[1]), "+f"(c[2]), "+f"(c[3])
        : "r"(a0), "r"(a1), "r"(a2), "r"(a3), "r"(b0), "r"(b1));
}

__global__ __launch_bounds__(128, 2)
void gemm_tf32_kernel(const float* __restrict__ A,
                      const float* __restrict__ B,
                      float* __restrict__ Cpart,
                      int M, int N, int ldA, int KP)
{
    __shared__ float As[3][BM * AS_STRIDE];
    __shared__ float Bs[3][BK * BS_STRIDE];

    const int tid  = threadIdx.x;
    const int m0   = blockIdx.y * BM;
    const int n0   = blockIdx.x * BN;
    const int z    = blockIdx.z;
    const int k0   = z * KP;
    const int warp = tid >> 5;
    const int lane = tid & 31;
    const int wm   = warp >> 1;     // 0..1
    const int wn   = warp & 1;      // 0..1
    const int g    = lane >> 2;     // 0..7
    const int tg   = lane & 3;      // 0..3

    // A staging: thread -> (row = tid/2, two 16B chunks)
    const int arow = tid >> 1;
    const int ac0  = (tid & 1) * 2;
    const bool apred = (m0 + arow) < M;
    const float* AgBase = A + (size_t)(m0 + arow) * ldA + k0 + ac0 * 4;

    // B staging: thread -> (row = tid/8, 4 chunks j*8 + (tid&7))
    const int brow = tid >> 3;                   // 0..15
    const int bc   = tid & 7;                    // 0..7
    const float* BgBase = B + (size_t)(k0 + brow) * N + n0 + bc * 4;

    float acc[2][8][4];
    #pragma unroll
    for (int mi = 0; mi < 2; ++mi)
        #pragma unroll
        for (int ni = 0; ni < 8; ++ni)
            #pragma unroll
            for (int q = 0; q < 4; ++q) acc[mi][ni][q] = 0.0f;

    const int T = KP / BK;

    auto stage = [&](int buf, int ts) {
        const size_t ka = (size_t)ts * BK;
        cp_async16(&As[buf][arow * AS_STRIDE + ac0 * 4],     AgBase + ka,     apred);
        cp_async16(&As[buf][arow * AS_STRIDE + ac0 * 4 + 4], AgBase + ka + 4, apred);
        const size_t kb = ka * (size_t)N;
        #pragma unroll
        for (int j = 0; j < 4; ++j)
            cp_async16(&Bs[buf][brow * BS_STRIDE + (j * 8 + bc) * 4],
                       BgBase + kb + j * 32, true);
    };

    stage(0, 0);
    asm volatile("cp.async.commit_group;");
    stage(1, 1);
    asm volatile("cp.async.commit_group;");

    int cur = 0;
    for (int t = 0; t < T; ++t) {
        asm volatile("cp.async.wait_group 1;");
        __syncthreads();

        if (t + 2 < T) {
            int nxt = cur + 2; if (nxt >= 3) nxt -= 3;
            stage(nxt, t + 2);
        }
        asm volatile("cp.async.commit_group;");

        const float* Asc = As[cur];
        const float* Bsc = Bs[cur];
        const uint32_t* Asu = (const uint32_t*)Asc;
        #pragma unroll
        for (int kk = 0; kk < BK; kk += 8) {
            uint32_t af[2][4], bf[8][2];
            #pragma unroll
            for (int mi = 0; mi < 2; ++mi) {
                const int rb = wm * 32 + mi * 16;
                af[mi][0] = Asu[(rb + g)     * AS_STRIDE + kk + tg];      // pre-rounded
                af[mi][1] = Asu[(rb + g + 8) * AS_STRIDE + kk + tg];
                af[mi][2] = Asu[(rb + g)     * AS_STRIDE + kk + tg + 4];
                af[mi][3] = Asu[(rb + g + 8) * AS_STRIDE + kk + tg + 4];
            }
            #pragma unroll
            for (int ni = 0; ni < 8; ++ni) {
                const int cb = wn * 64 + ni * 8;
                bf[ni][0] = f2tf32(Bsc[(kk + tg)     * BS_STRIDE + cb + g]);
                bf[ni][1] = f2tf32(Bsc[(kk + tg + 4) * BS_STRIDE + cb + g]);
            }
            #pragma unroll
            for (int mi = 0; mi < 2; ++mi)
                #pragma unroll
                for (int ni = 0; ni < 8; ++ni)
                    mma_tf32(acc[mi][ni], af[mi][0], af[mi][1], af[mi][2], af[mi][3],
                             bf[ni][0], bf[ni][1]);
        }
        ++cur; if (cur == 3) cur = 0;
    }

    // raw partial store (epilogue lives in the reduce kernel)
    float* Cz = Cpart + (size_t)z * M * N;
    #pragma unroll
    for (int mi = 0; mi < 2; ++mi) {
        #pragma unroll
        for (int ni = 0; ni < 8; ++ni) {
            const int row0 = m0 + wm * 32 + mi * 16 + g;
            const int col  = n0 + wn * 64 + ni * 8 + 2 * tg;
            if (row0 < M) {
                Cz[(size_t)row0 * N + col]     = acc[mi][ni][0];
                Cz[(size_t)row0 * N + col + 1] = acc[mi][ni][1];
            }
            if (row0 + 8 < M) {
                Cz[(size_t)(row0 + 8) * N + col]     = acc[mi][ni][2];
                Cz[(size_t)(row0 + 8) * N + col + 1] = acc[mi][ni][3];
            }
        }
    }
}

// reduce partials + bias + relu (+ optional tf32 round for downstream A use)
__global__ void gemm_reduce_kernel(const float* __restrict__ part,
                                   const float* __restrict__ bias,
                                   float* __restrict__ C,
                                   int M, int N, int do_round)
{
    int idx = blockIdx.x * blockDim.x + threadIdx.x;
    if (idx >= M * N) return;
    const int col = idx % N;
    float s = part[idx] + part[(size_t)M * N + idx];   // GSPLIT == 2, fixed order
    s = fmaxf(s + bias[col], 0.0f);
    if (do_round) s = __uint_as_float(f2tf32(s));
    C[idx] = s;
}

// ------------------------------- heads (fp32) -------------------------------
__global__ __launch_bounds__(128)
void heads_part_kernel(const float* __restrict__ fc7,
                       const float* __restrict__ Wl,
                       const float* __restrict__ Ws,
                       float* __restrict__ part)
{
    __shared__ float Ash[4][512];
    const int t  = threadIdx.x;
    const int kp = blockIdx.x;
    const int k0 = kp * (NFC / KSPLIT);
    const int r0 = blockIdx.y * 4;

    #pragma unroll
    for (int j = 0; j < 4; ++j) {
        const float4* src = (const float4*)(fc7 + (size_t)(r0 + j) * NFC + k0);
        ((float4*)&Ash[j][0])[t] = src[t];
    }
    __syncthreads();

    if (t < NHEAD) {
        const float* Wp; int ldw, col;
        if (t < NLOC) { Wp = Wl; ldw = NLOC;   col = t; }
        else          { Wp = Ws; ldw = NSCORE; col = t - NLOC; }
        const float* wptr = Wp + (size_t)k0 * ldw + col;

        float a0 = 0.f, a1 = 0.f, a2 = 0.f, a3 = 0.f;
        #pragma unroll 8
        for (int k = 0; k < 512; ++k) {
            const float w = __ldg(wptr + (size_t)k * ldw);
            a0 = fmaf(Ash[0][k], w, a0);
            a1 = fmaf(Ash[1][k], w, a1);
            a2 = fmaf(Ash[2][k], w, a2);
            a3 = fmaf(Ash[3][k], w, a3);
        }
        float* pp = part + (size_t)kp * (R_ROIS * NHEAD) + (size_t)r0 * NHEAD + t;
        pp[0 * NHEAD] = a0;
        pp[1 * NHEAD] = a1;
        pp[2 * NHEAD] = a2;
        pp[3 * NHEAD] = a3;
    }
}

__global__ void heads_reduce_kernel(const float* __restrict__ part,
                                    const float* __restrict__ bl,
                                    const float* __restrict__ bs,
                                    float* __restrict__ out)
{
    int idx = blockIdx.x * blockDim.x + threadIdx.x;
    if (idx >= R_ROIS * NHEAD) return;
    float s = 0.f;
    #pragma unroll
    for (int p = 0; p < KSPLIT; ++p)
        s += part[(size_t)p * (R_ROIS * NHEAD) + idx];
    const int roi = idx / NHEAD;
    const int c   = idx - roi * NHEAD;
    if (c < NLOC)
        out[(size_t)roi * NLOC + c] = s + bl[c];
    else
        out[(size_t)R_ROIS * NLOC + (size_t)roi * NSCORE + (c - NLOC)] = s + bs[c - NLOC];
}

// ------------------------------- launch -------------------------------------
extern "C" void kernel_launch(void* const* d_in, const int* in_sizes, int n_in,
                              void* d_out, int out_size)
{
    (void)in_sizes; (void)n_in; (void)out_size;
    const float* x     = (const float*)d_in[0];
    const float* rois  = (const float*)d_in[1];
    const float* W6    = (const float*)d_in[2];
    const float* b6    = (const float*)d_in[3];
    const float* W7    = (const float*)d_in[4];
    const float* b7    = (const float*)d_in[5];
    const float* Wl    = (const float*)d_in[6];
    const float* bl    = (const float*)d_in[7];
    const float* Ws    = (const float*)d_in[8];
    const float* bs    = (const float*)d_in[9];
    float* out = (float*)d_out;

    float *pool_p, *fc6_p, *fc7_p, *part_p, *hpart_p;
    cudaGetSymbolAddress((void**)&pool_p,  g_pool);
    cudaGetSymbolAddress((void**)&fc6_p,   g_fc6);
    cudaGetSymbolAddress((void**)&fc7_p,   g_fc7);
    cudaGetSymbolAddress((void**)&part_p,  g_part);
    cudaGetSymbolAddress((void**)&hpart_p, g_hpart);

    // 1) ROI adaptive maxpool (tf32-rounded output)
    {
        const int total = R_ROIS * NPOOL;
        roi_pool_kernel<<<(total + 255) / 256, 256>>>(x, rois, pool_p);
    }
    // 2) fc6 = relu(pool @ W6 + b6)   M=300 N=4096 K=25088, split-K=2
    {
        dim3 grid(NFC / BN, (R_ROIS + BM - 1) / BM, GSPLIT);   // (32, 5, 2)
        gemm_tf32_kernel<<<grid, 128>>>(pool_p, W6, part_p,
                                        R_ROIS, NFC, NPOOL, NPOOL / GSPLIT);
        const int tot = R_ROIS * NFC;
        gemm_reduce_kernel<<<(tot + 255) / 256, 256>>>(part_p, b6, fc6_p,
                                                       R_ROIS, NFC, 1 /*round*/);
    }
    // 3) fc7 = relu(fc6 @ W7 + b7)    M=300 N=4096 K=4096, split-K=2
    {
        dim3 grid(NFC / BN, (R_ROIS + BM - 1) / BM, GSPLIT);
        gemm_tf32_kernel<<<grid, 128>>>(fc6_p, W7, part_p,
                                        R_ROIS, NFC, NFC, NFC / GSPLIT);
        const int tot = R_ROIS * NFC;
        gemm_reduce_kernel<<<(tot + 255) / 256, 256>>>(part_p, b7, fc7_p,
                                                       R_ROIS, NFC, 0);
    }
    // 4) heads: split-K partials + deterministic reduce
    {
        dim3 grid(KSPLIT, R_ROIS / 4);
        heads_part_kernel<<<grid, 128>>>(fc7_p, Wl, Ws, hpart_p);
        heads_reduce_kernel<<<(R_ROIS * NHEAD + 255) / 256, 256>>>(hpart_p, bl, bs, out);
    }
}

// round 16
// speedup vs baseline: 3.2441x; 1.2683x over previous
#include <cuda_runtime.h>
#include <cuda_bf16.h>
#include <cstdint>

// ----------------------------------------------------------------------------
// VGG16 RoI head: pool -> fc6(relu) -> fc7(relu) -> {loc, score}
// GEMMs on mma.sync.m16n8k8.tf32 (sm_103 base ISA; tcgen05 'a'-features are
// unavailable in this toolchain — R14 ptxas evidence).
// R16: GSPLIT 2->4 (grid 640 -> 4 CTAs/SM, occupancy was grid-limited at
// 12.9%), heads KSPLIT 8->16. A operands pre-rounded tf32 (no A-cvt in loop).
// ----------------------------------------------------------------------------

#define R_ROIS   300
#define CCH      512
#define HF       50
#define WF       50
#define NPOOL    (CCH * 49)          // 25088
#define NFC      4096
#define NLOC     84
#define NSCORE   21
#define NHEAD    (NLOC + NSCORE)     // 105
#define KSPLIT   16                  // heads split-K
#define GSPLIT   4                   // gemm split-K

// -------------------- device scratch (no allocations allowed) ---------------
__device__ float g_pool [R_ROIS * NPOOL];            // ~30.1 MB
__device__ float g_fc6  [R_ROIS * NFC];              // ~4.9 MB
__device__ float g_fc7  [R_ROIS * NFC];              // ~4.9 MB
__device__ float g_part [GSPLIT * R_ROIS * NFC];     // ~19.7 MB gemm partials
__device__ float g_hpart[KSPLIT * R_ROIS * NHEAD];   // ~2.0 MB

__device__ __forceinline__ uint32_t f2tf32(float f) {
    uint32_t r;
    asm("cvt.rna.tf32.f32 %0, %1;" : "=r"(r) : "f"(f));
    return r;
}

// ----------------------------- ROI max pool ---------------------------------
__global__ void roi_pool_kernel(const float* __restrict__ feat,
                                const float* __restrict__ rois,
                                float* __restrict__ out)
{
    int idx = blockIdx.x * blockDim.x + threadIdx.x;
    if (idx >= R_ROIS * NPOOL) return;
    int r    = idx / NPOOL;
    int rem  = idx - r * NPOOL;
    int c    = rem / 49;
    int bin  = rem - c * 49;
    int by   = bin / 7;
    int bx   = bin - by * 7;

    int y1 = (int)(rois[r * 4 + 0] * 0.0625f);
    int x1 = (int)(rois[r * 4 + 1] * 0.0625f);
    int y2 = (int)(rois[r * 4 + 2] * 0.0625f);
    int x2 = (int)(rois[r * 4 + 3] * 0.0625f);
    int h = y2 - y1 + 1;
    int w = x2 - x1 + 1;

    int rs = y1 + (by * h) / 7;
    int re = y1 + ((by + 1) * h + 6) / 7;
    int cs = x1 + (bx * w) / 7;
    int ce = x1 + ((bx + 1) * w + 6) / 7;

    const float* fp = feat + c * (HF * WF);
    float m = -3.402823466e38f;
    for (int y = rs; y < re; ++y) {
        const float* rowp = fp + y * WF;
        for (int x = cs; x < ce; ++x)
            m = fmaxf(m, rowp[x]);
    }
    // pre-round to tf32 (identical numerics to in-GEMM A rounding)
    out[idx] = __uint_as_float(f2tf32(m));
}

// ---------------------- tf32 mma.sync GEMM (fp32 accum) ---------------------
// Cpart[z][M,N] = A[M, zKP:(z+1)KP] @ B[zKP:(z+1)KP, N]  (raw partials)
// Block tile 64x128, BK=16, 4 warps (2x2), warp tile 32x64.
// 3-stage cp.async pipeline, one __syncthreads per BK tile.
#define BM 64
#define BN 128
#define BK 16
#define AS_STRIDE 20
#define BS_STRIDE 136

__device__ __forceinline__ void cp_async16(float* smem_dst, const float* gmem_src, bool pred) {
    uint32_t s = (uint32_t)__cvta_generic_to_shared(smem_dst);
    int sz = pred ? 16 : 0;  // src-size 0 => zero-fill 16B
    asm volatile("cp.async.cg.shared.global [%0], [%1], 16, %2;"
                 :: "r"(s), "l"(gmem_src), "r"(sz));
}

__device__ __forceinline__ void mma_tf32(float c[4],
                                         uint32_t a0, uint32_t a1, uint32_t a2, uint32_t a3,
                                         uint32_t b0, uint32_t b1) {
    asm volatile(
        "mma.sync.aligned.m16n8k8.row.col.f32.tf32.tf32.f32 "
        "{%0,%1,%2,%3}, {%4,%5,%6,%7}, {%8,%9}, {%0,%1,%2,%3};"
        : "+f"(c[0]), "+f"(c[1]), "+f"(c[2]), "+f"(c[3])
        : "r"(a0), "r"(a1), "r"(a2), "r"(a3), "r"(b0), "r"(b1));
}

__global__ __launch_bounds__(128, 4)
void gemm_tf32_kernel(const float* __restrict__ A,
                      const float* __restrict__ B,
                      float* __restrict__ Cpart,
                      int M, int N, int ldA, int KP)
{
    __shared__ float As[3][BM * AS_STRIDE];
    __shared__ float Bs[3][BK * BS_STRIDE];

    const int tid  = threadIdx.x;
    const int m0   = blockIdx.y * BM;
    const int n0   = blockIdx.x * BN;
    const int z    = blockIdx.z;
    const int k0   = z * KP;
    const int warp = tid >> 5;
    const int lane = tid & 31;
    const int wm   = warp >> 1;
    const int wn   = warp & 1;
    const int g    = lane >> 2;
    const int tg   = lane & 3;

    const int arow = tid >> 1;
    const int ac0  = (tid & 1) * 2;
    const bool apred = (m0 + arow) < M;
    const float* AgBase = A + (size_t)(m0 + arow) * ldA + k0 + ac0 * 4;

    const int brow = tid >> 3;
    const int bc   = tid & 7;
    const float* BgBase = B + (size_t)(k0 + brow) * N + n0 + bc * 4;

    float acc[2][8][4];
    #pragma unroll
    for (int mi = 0; mi < 2; ++mi)
        #pragma unroll
        for (int ni = 0; ni < 8; ++ni)
            #pragma unroll
            for (int q = 0; q < 4; ++q) acc[mi][ni][q] = 0.0f;

    const int T = KP / BK;

    auto stage = [&](int buf, int ts) {
        const size_t ka = (size_t)ts * BK;
        cp_async16(&As[buf][arow * AS_STRIDE + ac0 * 4],     AgBase + ka,     apred);
        cp_async16(&As[buf][arow * AS_STRIDE + ac0 * 4 + 4], AgBase + ka + 4, apred);
        const size_t kb = ka * (size_t)N;
        #pragma unroll
        for (int j = 0; j < 4; ++j)
            cp_async16(&Bs[buf][brow * BS_STRIDE + (j * 8 + bc) * 4],
                       BgBase + kb + j * 32, true);
    };

    stage(0, 0);
    asm volatile("cp.async.commit_group;");
    stage(1, 1);
    asm volatile("cp.async.commit_group;");

    int cur = 0;
    for (int t = 0; t < T; ++t) {
        asm volatile("cp.async.wait_group 1;");
        __syncthreads();

        if (t + 2 < T) {
            int nxt = cur + 2; if (nxt >= 3) nxt -= 3;
            stage(nxt, t + 2);
        }
        asm volatile("cp.async.commit_group;");

        const float* Bsc = Bs[cur];
        const uint32_t* Asu = (const uint32_t*)As[cur];
        #pragma unroll
        for (int kk = 0; kk < BK; kk += 8) {
            uint32_t af[2][4], bf[8][2];
            #pragma unroll
            for (int mi = 0; mi < 2; ++mi) {
                const int rb = wm * 32 + mi * 16;
                af[mi][0] = Asu[(rb + g)     * AS_STRIDE + kk + tg];   // pre-rounded
                af[mi][1] = Asu[(rb + g + 8) * AS_STRIDE + kk + tg];
                af[mi][2] = Asu[(rb + g)     * AS_STRIDE + kk + tg + 4];
                af[mi][3] = Asu[(rb + g + 8) * AS_STRIDE + kk + tg + 4];
            }
            #pragma unroll
            for (int ni = 0; ni < 8; ++ni) {
                const int cb = wn * 64 + ni * 8;
                bf[ni][0] = f2tf32(Bsc[(kk + tg)     * BS_STRIDE + cb + g]);
                bf[ni][1] = f2tf32(Bsc[(kk + tg + 4) * BS_STRIDE + cb + g]);
            }
            #pragma unroll
            for (int mi = 0; mi < 2; ++mi)
                #pragma unroll
                for (int ni = 0; ni < 8; ++ni)
                    mma_tf32(acc[mi][ni], af[mi][0], af[mi][1], af[mi][2], af[mi][3],
                             bf[ni][0], bf[ni][1]);
        }
        ++cur; if (cur == 3) cur = 0;
    }

    float* Cz = Cpart + (size_t)z * M * N;
    #pragma unroll
    for (int mi = 0; mi < 2; ++mi) {
        #pragma unroll
        for (int ni = 0; ni < 8; ++ni) {
            const int row0 = m0 + wm * 32 + mi * 16 + g;
            const int col  = n0 + wn * 64 + ni * 8 + 2 * tg;
            if (row0 < M) {
                Cz[(size_t)row0 * N + col]     = acc[mi][ni][0];
                Cz[(size_t)row0 * N + col + 1] = acc[mi][ni][1];
            }
            if (row0 + 8 < M) {
                Cz[(size_t)(row0 + 8) * N + col]     = acc[mi][ni][2];
                Cz[(size_t)(row0 + 8) * N + col + 1] = acc[mi][ni][3];
            }
        }
    }
}

// reduce GSPLIT partials + bias + relu (+ optional tf32 round)
__global__ void gemm_reduce_kernel(const float* __restrict__ part,
                                   const float* __restrict__ bias,
                                   float* __restrict__ C,
                                   int M, int N, int do_round)
{
    int idx = blockIdx.x * blockDim.x + threadIdx.x;
    if (idx >= M * N) return;
    const int col = idx % N;
    const size_t stride = (size_t)M * N;
    float s = part[idx];
    #pragma unroll
    for (int p = 1; p < GSPLIT; ++p)
        s += part[p * stride + idx];   // fixed order: deterministic
    s = fmaxf(s + bias[col], 0.0f);
    if (do_round) s = __uint_as_float(f2tf32(s));
    C[idx] = s;
}

// ------------------------------- heads (fp32) -------------------------------
// Split-K=16: grid (16, 75); block = 4 rois x 256-wide K slice.
#define HKW (NFC / KSPLIT)   // 256
__global__ __launch_bounds__(128)
void heads_part_kernel(const float* __restrict__ fc7,
                       const float* __restrict__ Wl,
                       const float* __restrict__ Ws,
                       float* __restrict__ part)
{
    __shared__ float Ash[4][HKW];
    const int t  = threadIdx.x;
    const int kp = blockIdx.x;
    const int k0 = kp * HKW;
    const int r0 = blockIdx.y * 4;

    // stage fc7[r0..r0+3][k0..k0+HKW): 64 float4 per roi, 128 threads
    {
        const int j = t >> 6;            // 0..1 -> rois {j, j+2}
        const int i = t & 63;            // float4 index
        const float4* s0 = (const float4*)(fc7 + (size_t)(r0 + j) * NFC + k0);
        const float4* s1 = (const float4*)(fc7 + (size_t)(r0 + j + 2) * NFC + k0);
        ((float4*)&Ash[j][0])[i]     = s0[i];
        ((float4*)&Ash[j + 2][0])[i] = s1[i];
    }
    __syncthreads();

    if (t < NHEAD) {
        const float* Wp; int ldw, col;
        if (t < NLOC) { Wp = Wl; ldw = NLOC;   col = t; }
        else          { Wp = Ws; ldw = NSCORE; col = t - NLOC; }
        const float* wptr = Wp + (size_t)k0 * ldw + col;

        float a0 = 0.f, a1 = 0.f, a2 = 0.f, a3 = 0.f;
        #pragma unroll 8
        for (int k = 0; k < HKW; ++k) {
            const float w = __ldg(wptr + (size_t)k * ldw);
            a0 = fmaf(Ash[0][k], w, a0);
            a1 = fmaf(Ash[1][k], w, a1);
            a2 = fmaf(Ash[2][k], w, a2);
            a3 = fmaf(Ash[3][k], w, a3);
        }
        float* pp = part + (size_t)kp * (R_ROIS * NHEAD) + (size_t)r0 * NHEAD + t;
        pp[0 * NHEAD] = a0;
        pp[1 * NHEAD] = a1;
        pp[2 * NHEAD] = a2;
        pp[3 * NHEAD] = a3;
    }
}

__global__ void heads_reduce_kernel(const float* __restrict__ part,
                                    const float* __restrict__ bl,
                                    const float* __restrict__ bs,
                                    float* __restrict__ out)
{
    int idx = blockIdx.x * blockDim.x + threadIdx.x;
    if (idx >= R_ROIS * NHEAD) return;
    float s = 0.f;
    #pragma unroll
    for (int p = 0; p < KSPLIT; ++p)
        s += part[(size_t)p * (R_ROIS * NHEAD) + idx];
    const int roi = idx / NHEAD;
    const int c   = idx - roi * NHEAD;
    if (c < NLOC)
        out[(size_t)roi * NLOC + c] = s + bl[c];
    else
        out[(size_t)R_ROIS * NLOC + (size_t)roi * NSCORE + (c - NLOC)] = s + bs[c - NLOC];
}

// ------------------------------- launch -------------------------------------
extern "C" void kernel_launch(void* const* d_in, const int* in_sizes, int n_in,
                              void* d_out, int out_size)
{
    (void)in_sizes; (void)n_in; (void)out_size;
    const float* x     = (const float*)d_in[0];
    const float* rois  = (const float*)d_in[1];
    const float* W6    = (const float*)d_in[2];
    const float* b6    = (const float*)d_in[3];
    const float* W7    = (const float*)d_in[4];
    const float* b7    = (const float*)d_in[5];
    const float* Wl    = (const float*)d_in[6];
    const float* bl    = (const float*)d_in[7];
    const float* Ws    = (const float*)d_in[8];
    const float* bs    = (const float*)d_in[9];
    float* out = (float*)d_out;

    float *pool_p, *fc6_p, *fc7_p, *part_p, *hpart_p;
    cudaGetSymbolAddress((void**)&pool_p,  g_pool);
    cudaGetSymbolAddress((void**)&fc6_p,   g_fc6);
    cudaGetSymbolAddress((void**)&fc7_p,   g_fc7);
    cudaGetSymbolAddress((void**)&part_p,  g_part);
    cudaGetSymbolAddress((void**)&hpart_p, g_hpart);

    // 1) ROI adaptive maxpool (tf32-rounded output)
    {
        const int total = R_ROIS * NPOOL;
        roi_pool_kernel<<<(total + 255) / 256, 256>>>(x, rois, pool_p);
    }
    // 2) fc6 = relu(pool @ W6 + b6)   M=300 N=4096 K=25088, split-K=4
    {
        dim3 grid(NFC / BN, (R_ROIS + BM - 1) / BM, GSPLIT);   // (32, 5, 4)
        gemm_tf32_kernel<<<grid, 128>>>(pool_p, W6, part_p,
                                        R_ROIS, NFC, NPOOL, NPOOL / GSPLIT);
        const int tot = R_ROIS * NFC;
        gemm_reduce_kernel<<<(tot + 255) / 256, 256>>>(part_p, b6, fc6_p,
                                                       R_ROIS, NFC, 1 /*round*/);
    }
    // 3) fc7 = relu(fc6 @ W7 + b7)    M=300 N=4096 K=4096, split-K=4
    {
        dim3 grid(NFC / BN, (R_ROIS + BM - 1) / BM, GSPLIT);
        gemm_tf32_kernel<<<grid, 128>>>(fc6_p, W7, part_p,
                                        R_ROIS, NFC, NFC, NFC / GSPLIT);
        const int tot = R_ROIS * NFC;
        gemm_reduce_kernel<<<(tot + 255) / 256, 256>>>(part_p, b7, fc7_p,
                                                       R_ROIS, NFC, 0);
    }
    // 4) heads: split-K=16 partials + deterministic reduce
    {
        dim3 grid(KSPLIT, R_ROIS / 4);
        heads_part_kernel<<<grid, 128>>>(fc7_p, Wl, Ws, hpart_p);
        heads_reduce_kernel<<<(R_ROIS * NHEAD + 255) / 256, 256>>>(hpart_p, bl, bs, out);
    }
}